// round 1
// baseline (speedup 1.0000x reference)
#include <cuda_runtime.h>
#include <math.h>

// Problem constants
#define NB    256      // batch N
#define CC    256      // channels
#define TT    64       // time
#define VN    7        // graph nodes
#define CT    16384    // C*T (GEMM K)
#define CTV   114688   // CT*V
#define EOUT  256      // GEMM N (output features)
#define NV    1792     // NB*VN (GEMM M)
#define ALPHA 0.2f

// Scratch (no cudaMalloc allowed)
__device__ float g_Wh[NV * EOUT];      // 1792*256 fp32 = 1.84 MB
__device__ float g_adjn[VN * VN];      // normalized adjacency

// ---------------------------------------------------------------------------
// Stage 1: Wh[m, o] = sum_k A[m,k] * W[k,o]
//   m = n*7+v, k = c*64+t, A[m,k] = h[n*CTV + k*7 + v]
// Tiled SIMT GEMM: 64x64 block tile, K-tile 16, 4x4 per thread, 256 threads.
// Grid: (1792/64, 256/64) = (28, 4)
// ---------------------------------------------------------------------------
__global__ __launch_bounds__(256) void gemm_kernel(const float* __restrict__ h,
                                                   const float* __restrict__ W) {
    __shared__ float As[16][64];
    __shared__ float Bs[16][64];

    const int tid = threadIdx.x;
    const int m0  = blockIdx.x * 64;
    const int o0  = blockIdx.y * 64;
    const int tm  = (tid >> 4) << 2;   // 0..60 step 4
    const int tn  = (tid & 15) << 2;   // 0..60 step 4

    float acc[4][4];
#pragma unroll
    for (int i = 0; i < 4; i++)
#pragma unroll
        for (int j = 0; j < 4; j++) acc[i][j] = 0.f;

    // A-load mapping: element e = tid + r*256 ; am = e&63 (row), ak = e>>6 (k)
    const int am  = tid & 63;
    const int ak0 = tid >> 6;               // 0..3, element r uses ak0 + 4r
    const int gm  = m0 + am;
    const int an  = gm / 7;
    const int av  = gm - an * 7;
    const float* hA = h + (long long)an * CTV + av;

    // B-load mapping
    const int bo  = tid & 63;
    const int bk0 = tid >> 6;
    const float* WB = W + bk0 * EOUT + o0 + bo;

    for (int k0 = 0; k0 < CT; k0 += 16) {
#pragma unroll
        for (int r = 0; r < 4; r++) {
            As[ak0 + r * 4][am] = hA[(k0 + ak0 + r * 4) * 7];
            Bs[bk0 + r * 4][bo] = WB[(k0 + r * 4) * EOUT];
        }
        __syncthreads();
#pragma unroll
        for (int k = 0; k < 16; k++) {
            const float4 a4 = *reinterpret_cast<const float4*>(&As[k][tm]);
            const float4 b4 = *reinterpret_cast<const float4*>(&Bs[k][tn]);
            const float ar[4] = {a4.x, a4.y, a4.z, a4.w};
            const float br[4] = {b4.x, b4.y, b4.z, b4.w};
#pragma unroll
            for (int i = 0; i < 4; i++)
#pragma unroll
                for (int j = 0; j < 4; j++)
                    acc[i][j] = fmaf(ar[i], br[j], acc[i][j]);
        }
        __syncthreads();
    }

#pragma unroll
    for (int i = 0; i < 4; i++) {
#pragma unroll
        for (int j = 0; j < 4; j++) {
            g_Wh[(m0 + tm + i) * EOUT + o0 + tn + j] = acc[i][j];
        }
    }
}

// ---------------------------------------------------------------------------
// Stage 2: normalized adjacency (tiny, one block)
// adj = Bp + 1e-6 + I ; scale to [0,1] via (adj-min)/(max-min)
// D = diag(rowsum) ; adjn = D^-1/2 adj D^-1/2
// ---------------------------------------------------------------------------
__global__ void adj_kernel(const float* __restrict__ Bp) {
    __shared__ float adj[49];
    __shared__ float amin, amax;
    __shared__ float dis[7];
    const int t = threadIdx.x;

    if (t < 49) {
        const int i = t / 7, j = t - (t / 7) * 7;
        adj[t] = Bp[t] + 1e-6f + (i == j ? 1.f : 0.f);
    }
    __syncthreads();
    if (t == 0) {
        float mn = adj[0], mx = adj[0];
        for (int q = 1; q < 49; q++) { mn = fminf(mn, adj[q]); mx = fmaxf(mx, adj[q]); }
        amin = mn; amax = mx;
    }
    __syncthreads();
    if (t < 49) adj[t] = (adj[t] - amin) / (amax - amin);
    __syncthreads();
    if (t < 7) {
        float s = 0.f;
        for (int j = 0; j < 7; j++) s += adj[t * 7 + j];
        dis[t] = 1.0f / sqrtf(s);
    }
    __syncthreads();
    if (t < 49) {
        const int i = t / 7, j = t - (t / 7) * 7;
        g_adjn[t] = dis[i] * adj[t] * dis[j];
    }
}

// ---------------------------------------------------------------------------
// Stage 3: per-batch attention epilogue. One block per n, 256 threads.
//  s1[v] = Wh[n,v,:]·a1 ; s2[v] = Wh[n,v,:]·a2
//  e[v,u] = leaky(s1[v]+s2[u]) ; softmax over u ; att = adjn @ sm
//  h' = att @ Wh[n] ; out = elu(h')
// ---------------------------------------------------------------------------
__global__ __launch_bounds__(256) void attn_kernel(const float* __restrict__ a,
                                                   float* __restrict__ out) {
    const int n = blockIdx.x;
    const int t = threadIdx.x;
    const float* Wh = g_Wh + n * (VN * EOUT);

    __shared__ float s1[8], s2[8];
    __shared__ float sm[7][7];
    __shared__ float att[7][7];

    const int w = t >> 5, l = t & 31;
    if (w < 7) {
        float p1 = 0.f, p2 = 0.f;
#pragma unroll
        for (int o = l; o < EOUT; o += 32) {
            const float x = Wh[w * EOUT + o];
            p1 += x * a[o];
            p2 += x * a[EOUT + o];
        }
#pragma unroll
        for (int off = 16; off > 0; off >>= 1) {
            p1 += __shfl_down_sync(0xffffffffu, p1, off);
            p2 += __shfl_down_sync(0xffffffffu, p2, off);
        }
        if (l == 0) { s1[w] = p1; s2[w] = p2; }
    }
    __syncthreads();

    if (t < 7) {
        float e[7];
        float mx = -1e30f;
#pragma unroll
        for (int u = 0; u < 7; u++) {
            float x = s1[t] + s2[u];
            x = (x > 0.f) ? x : ALPHA * x;
            e[u] = x;
            mx = fmaxf(mx, x);
        }
        float s = 0.f;
#pragma unroll
        for (int u = 0; u < 7; u++) { e[u] = expf(e[u] - mx); s += e[u]; }
        const float inv = 1.f / s;
#pragma unroll
        for (int u = 0; u < 7; u++) sm[t][u] = e[u] * inv;
    }
    __syncthreads();

    if (t < 49) {
        const int i = t / 7, j = t - (t / 7) * 7;
        float s = 0.f;
#pragma unroll
        for (int q = 0; q < 7; q++) s += g_adjn[i * 7 + q] * sm[q][j];
        att[i][j] = s;
    }
    __syncthreads();

    float whu[7];
#pragma unroll
    for (int u = 0; u < 7; u++) whu[u] = Wh[u * EOUT + t];

#pragma unroll
    for (int v = 0; v < 7; v++) {
        float hp = 0.f;
#pragma unroll
        for (int u = 0; u < 7; u++) hp = fmaf(att[v][u], whu[u], hp);
        const float r = (hp > 0.f) ? hp : expm1f(hp);
        out[n * (VN * EOUT) + v * EOUT + t] = r;
    }
}

// ---------------------------------------------------------------------------
extern "C" void kernel_launch(void* const* d_in, const int* in_sizes, int n_in,
                              void* d_out, int out_size) {
    const float* h  = (const float*)d_in[0];
    const float* W  = (const float*)d_in[1];
    const float* a  = (const float*)d_in[2];
    const float* Bp = (const float*)d_in[3];
    float* out = (float*)d_out;

    dim3 grid(NV / 64, EOUT / 64);       // (28, 4)
    gemm_kernel<<<grid, 256>>>(h, W);
    adj_kernel<<<1, 64>>>(Bp);
    attn_kernel<<<NB, 256>>>(a, out);
}

// round 6
// speedup vs baseline: 3.5485x; 3.5485x over previous
#include <cuda_runtime.h>
#include <cuda_fp16.h>
#include <mma.h>
#include <math.h>
#include <stdint.h>

using namespace nvcuda;

// Problem constants
#define NB    256
#define VN    7
#define CT    16384
#define CTV   114688      // CT*VN
#define EOUT  256
#define NV    1792        // NB*VN
#define ALPHA 0.2f

// GEMM tiling
#define KSPLIT  4
#define KSLICE  4096      // CT/KSPLIT
#define BM      128
#define BN      128
#define BK      32
#define NST     (KSLICE / BK)   // 128 stages
#define SA      40               // smem row stride in halves (80B, mult of 16B)
#define ABUFH   (BM * SA)        // 5120 halves per buffer

// Scratch (static device arrays; no cudaMalloc allowed)
__device__ __half g_Wth[EOUT * CT];            // 8 MB  W^T hi (fp16)
__device__ __half g_Wtl[EOUT * CT];            // 8 MB  W^T lo (fp16)
__device__ float  g_Whp[KSPLIT * NV * EOUT];   // 7.3 MB split-K partials
__device__ float  g_Wh[NV * EOUT];             // 1.84 MB
__device__ float  g_adjn[VN * VN];

// ---------------------------------------------------------------------------
// W transpose + fp16 hi/lo split: g_Wth/g_Wtl[o][k] = split(W[k][o])
// ---------------------------------------------------------------------------
__global__ __launch_bounds__(256) void transpose_W(const float* __restrict__ W) {
    __shared__ float tile[32][33];
    const int k0 = blockIdx.x * 32, o0 = blockIdx.y * 32;
    const int tx = threadIdx.x & 31, ty = threadIdx.x >> 5;
#pragma unroll
    for (int r = 0; r < 32; r += 8)
        tile[ty + r][tx] = W[(size_t)(k0 + ty + r) * EOUT + o0 + tx];
    __syncthreads();
#pragma unroll
    for (int r = 0; r < 32; r += 8) {
        const float x = tile[tx][ty + r];
        const __half hx = __float2half_rn(x);
        const __half lx = __float2half_rn(x - __half2float(hx));
        const size_t idx = (size_t)(o0 + ty + r) * CT + k0 + tx;
        g_Wth[idx] = hx;
        g_Wtl[idx] = lx;
    }
}

// ---------------------------------------------------------------------------
// fp16x3 GEMM via wmma, split-K.
//   A[m,k] = h[n*CTV + k*7 + v]  (m = n*7+v), B[k,o] from g_Wth/g_Wtl.
// Grid (14, 2, 4), 256 threads = 8 warps; warp tile 64x32 (4x2 wmma tiles).
// ---------------------------------------------------------------------------
__global__ __launch_bounds__(256, 1) void gemm_mma(const float* __restrict__ h) {
    extern __shared__ __half smh[];
    __half* const AHb = smh;                 // 2 stages
    __half* const ALb = smh + 2 * ABUFH;
    __half* const BHb = smh + 4 * ABUFH;
    __half* const BLb = smh + 6 * ABUFH;

    const int tid = threadIdx.x, wid = tid >> 5, lane = tid & 31;
    const int m0 = blockIdx.x * BM, o0 = blockIdx.y * BN, ks = blockIdx.z;
    const int kbase = ks * KSLICE;

    // ---- A gather: warp w, step r handles smem row (8r+w), lane = kk ----
    // global idx = n*CTV + (k0+kk)*7 + v  with m = m0 + row, n=m/7, v=m%7
    int aBase[16];   // n*CTV + v + lane*7  (add k0*7 at use)
    int dstAr[16];   // smem half offset
#pragma unroll
    for (int r = 0; r < 16; r++) {
        const int row = 8 * r + wid;
        const int m = m0 + row;
        const int n = m / 7, v = m - n * 7;
        aBase[r] = n * CTV + v + lane * 7;
        dstAr[r] = row * SA + lane;
    }
    // ---- B geometry: j = r*256+tid over 1024; o = j>>3, kq = j&7 (4 halves) ----
    int boff[4], dstB[4];
#pragma unroll
    for (int r = 0; r < 4; r++) {
        const int j = r * 256 + tid;
        const int o = j >> 3, kq = j & 7;
        boff[r] = (o0 + o) * CT + kq * 4;   // half index (k base added at use)
        dstB[r] = o * 20 + kq * 2;          // word index (row = 20 words)
    }

    // ---- prefetch stage 0 ----
    float aR[16];
    uint2 bHR[4], bLR[4];
    {
        const int k7 = kbase * 7;
#pragma unroll
        for (int r = 0; r < 16; r++) aR[r] = h[(size_t)(aBase[r] + k7)];
#pragma unroll
        for (int r = 0; r < 4; r++) {
            bHR[r] = *reinterpret_cast<const uint2*>(&g_Wth[(size_t)boff[r] + kbase]);
            bLR[r] = *reinterpret_cast<const uint2*>(&g_Wtl[(size_t)boff[r] + kbase]);
        }
    }

    wmma::fragment<wmma::accumulator, 16, 16, 16, float> acc[4][2];
#pragma unroll
    for (int mf = 0; mf < 4; mf++)
#pragma unroll
        for (int nf = 0; nf < 2; nf++) wmma::fill_fragment(acc[mf][nf], 0.f);

    const int mw = (wid >> 2) * 64;   // 0 or 64
    const int nw = (wid & 3) * 32;    // 0,32,64,96

#pragma unroll 1
    for (int s = 0; s < NST; s++) {
        const int buf = s & 1;
        __half* const ah = AHb + buf * ABUFH;
        __half* const al = ALb + buf * ABUFH;
        __half* const bh = BHb + buf * ABUFH;
        __half* const bl = BLb + buf * ABUFH;

        // STS A (fp16 hi/lo split) — full coverage by construction
#pragma unroll
        for (int r = 0; r < 16; r++) {
            const float x = aR[r];
            const __half hx = __float2half_rn(x);
            ah[dstAr[r]] = hx;
            al[dstAr[r]] = __float2half_rn(x - __half2float(hx));
        }
        // STS B
        uint32_t* const bh32 = reinterpret_cast<uint32_t*>(bh);
        uint32_t* const bl32 = reinterpret_cast<uint32_t*>(bl);
#pragma unroll
        for (int r = 0; r < 4; r++) {
            *reinterpret_cast<uint2*>(&bh32[dstB[r]]) = bHR[r];
            *reinterpret_cast<uint2*>(&bl32[dstB[r]]) = bLR[r];
        }
        __syncthreads();

        // prefetch next stage
        if (s + 1 < NST) {
            const int kn = kbase + (s + 1) * BK;
            const int k7 = kn * 7;
#pragma unroll
            for (int r = 0; r < 16; r++) aR[r] = h[(size_t)(aBase[r] + k7)];
#pragma unroll
            for (int r = 0; r < 4; r++) {
                bHR[r] = *reinterpret_cast<const uint2*>(&g_Wth[(size_t)boff[r] + kn]);
                bLR[r] = *reinterpret_cast<const uint2*>(&g_Wtl[(size_t)boff[r] + kn]);
            }
        }

        // compute: 2 k-steps of 16
#pragma unroll
        for (int c = 0; c < 2; c++) {
            const int kk = c * 16;
            wmma::fragment<wmma::matrix_a, 16, 16, 16, __half, wmma::row_major> aH[4], aL[4];
#pragma unroll
            for (int mf = 0; mf < 4; mf++) {
                wmma::load_matrix_sync(aH[mf], ah + (mw + mf * 16) * SA + kk, SA);
                wmma::load_matrix_sync(aL[mf], al + (mw + mf * 16) * SA + kk, SA);
            }
            wmma::fragment<wmma::matrix_b, 16, 16, 16, __half, wmma::col_major> bH[2], bL[2];
#pragma unroll
            for (int nf = 0; nf < 2; nf++) {
                wmma::load_matrix_sync(bH[nf], bh + (nw + nf * 16) * SA + kk, SA);
                wmma::load_matrix_sync(bL[nf], bl + (nw + nf * 16) * SA + kk, SA);
            }
#pragma unroll
            for (int mf = 0; mf < 4; mf++)
#pragma unroll
                for (int nf = 0; nf < 2; nf++) {
                    wmma::mma_sync(acc[mf][nf], aH[mf], bH[nf], acc[mf][nf]);
                    wmma::mma_sync(acc[mf][nf], aH[mf], bL[nf], acc[mf][nf]);
                    wmma::mma_sync(acc[mf][nf], aL[mf], bH[nf], acc[mf][nf]);
                }
        }
        __syncthreads();
    }

    // epilogue: store partials
#pragma unroll
    for (int mf = 0; mf < 4; mf++)
#pragma unroll
        for (int nf = 0; nf < 2; nf++) {
            float* dst = g_Whp + ((size_t)ks * NV + m0 + mw + mf * 16) * EOUT
                       + o0 + nw + nf * 16;
            wmma::store_matrix_sync(dst, acc[mf][nf], EOUT, wmma::mem_row_major);
        }
}

// ---------------------------------------------------------------------------
// Split-K reduction
// ---------------------------------------------------------------------------
__global__ __launch_bounds__(256) void reduce_k() {
    const int i = blockIdx.x * 256 + threadIdx.x;
    const float4* p = reinterpret_cast<const float4*>(g_Whp);
    float4 s = p[i];
#pragma unroll
    for (int k = 1; k < KSPLIT; k++) {
        const float4 t = p[(size_t)k * (NV * EOUT / 4) + i];
        s.x += t.x; s.y += t.y; s.z += t.z; s.w += t.w;
    }
    reinterpret_cast<float4*>(g_Wh)[i] = s;
}

// ---------------------------------------------------------------------------
// Adjacency normalization (tiny)
// ---------------------------------------------------------------------------
__global__ void adj_kernel(const float* __restrict__ Bp) {
    __shared__ float adj[49];
    __shared__ float amin, amax;
    __shared__ float dis[7];
    const int t = threadIdx.x;
    if (t < 49) {
        const int i = t / 7, j = t - (t / 7) * 7;
        adj[t] = Bp[t] + 1e-6f + (i == j ? 1.f : 0.f);
    }
    __syncthreads();
    if (t == 0) {
        float mn = adj[0], mx = adj[0];
        for (int s = 1; s < 49; s++) { mn = fminf(mn, adj[s]); mx = fmaxf(mx, adj[s]); }
        amin = mn; amax = mx;
    }
    __syncthreads();
    if (t < 49) adj[t] = (adj[t] - amin) / (amax - amin);
    __syncthreads();
    if (t < 7) {
        float s = 0.f;
        for (int j = 0; j < 7; j++) s += adj[t * 7 + j];
        dis[t] = 1.0f / sqrtf(s);
    }
    __syncthreads();
    if (t < 49) {
        const int i = t / 7, j = t - (t / 7) * 7;
        g_adjn[t] = dis[i] * adj[t] * dis[j];
    }
}

// ---------------------------------------------------------------------------
// Per-batch attention epilogue
// ---------------------------------------------------------------------------
__global__ __launch_bounds__(256) void attn_kernel(const float* __restrict__ a,
                                                   float* __restrict__ out) {
    const int n = blockIdx.x;
    const int t = threadIdx.x;
    const float* Wh = g_Wh + n * (VN * EOUT);

    __shared__ float s1[8], s2[8];
    __shared__ float smx[7][7];
    __shared__ float att[7][7];

    const int w = t >> 5, l = t & 31;
    if (w < 7) {
        float p1 = 0.f, p2 = 0.f;
#pragma unroll
        for (int o = l; o < EOUT; o += 32) {
            const float x = Wh[w * EOUT + o];
            p1 += x * a[o];
            p2 += x * a[EOUT + o];
        }
#pragma unroll
        for (int off = 16; off > 0; off >>= 1) {
            p1 += __shfl_down_sync(0xffffffffu, p1, off);
            p2 += __shfl_down_sync(0xffffffffu, p2, off);
        }
        if (l == 0) { s1[w] = p1; s2[w] = p2; }
    }
    __syncthreads();

    if (t < 7) {
        float e[7];
        float mx = -1e30f;
#pragma unroll
        for (int u = 0; u < 7; u++) {
            float x = s1[t] + s2[u];
            x = (x > 0.f) ? x : ALPHA * x;
            e[u] = x;
            mx = fmaxf(mx, x);
        }
        float s = 0.f;
#pragma unroll
        for (int u = 0; u < 7; u++) { e[u] = expf(e[u] - mx); s += e[u]; }
        const float inv = 1.f / s;
#pragma unroll
        for (int u = 0; u < 7; u++) smx[t][u] = e[u] * inv;
    }
    __syncthreads();

    if (t < 49) {
        const int i = t / 7, j = t - (t / 7) * 7;
        float s = 0.f;
#pragma unroll
        for (int u = 0; u < 7; u++) s += g_adjn[i * 7 + u] * smx[u][j];
        att[i][j] = s;
    }
    __syncthreads();

    float whu[7];
#pragma unroll
    for (int u = 0; u < 7; u++) whu[u] = Wh[u * EOUT + t];

#pragma unroll
    for (int v = 0; v < 7; v++) {
        float hp = 0.f;
#pragma unroll
        for (int u = 0; u < 7; u++) hp = fmaf(att[v][u], whu[u], hp);
        const float r = (hp > 0.f) ? hp : expm1f(hp);
        out[n * (VN * EOUT) + v * EOUT + t] = r;
    }
}

// ---------------------------------------------------------------------------
extern "C" void kernel_launch(void* const* d_in, const int* in_sizes, int n_in,
                              void* d_out, int out_size) {
    const float* h  = (const float*)d_in[0];
    const float* W  = (const float*)d_in[1];
    const float* a  = (const float*)d_in[2];
    const float* Bp = (const float*)d_in[3];
    float* out = (float*)d_out;

    const int smem_bytes = 8 * ABUFH * 2;   // 81920 bytes
    cudaFuncSetAttribute(gemm_mma, cudaFuncAttributeMaxDynamicSharedMemorySize, smem_bytes);

    transpose_W<<<dim3(CT / 32, EOUT / 32), 256>>>(W);
    gemm_mma<<<dim3(NV / BM, EOUT / BN, KSPLIT), 256, smem_bytes>>>(h);
    reduce_k<<<NV * EOUT / 4 / 256, 256>>>();
    adj_kernel<<<1, 64>>>(Bp);
    attn_kernel<<<NB, 256>>>(a, out);
}

// round 7
// speedup vs baseline: 6.0956x; 1.7178x over previous
#include <cuda_runtime.h>
#include <cuda_fp16.h>
#include <mma.h>
#include <math.h>
#include <stdint.h>

using namespace nvcuda;

// Problem constants
#define NB    256
#define VN    7
#define CT    16384
#define CTV   114688      // CT*VN
#define EOUT  256
#define NV    1792        // NB*VN
#define ALPHA 0.2f

// GEMM tiling
#define KSPLIT  8
#define KSLICE  2048      // CT/KSPLIT
#define BM      128
#define BN      256
#define BK      32
#define NST     (KSLICE / BK)   // 64 stages
#define SA      40               // smem row stride in halves (80B = 5x16B)
#define ABUFH   (BM * SA)        // A buffer halves (5120)
#define BBUFH   (BN * SA)        // B buffer halves (10240)

// Scratch (static device arrays; no cudaMalloc allowed)
__device__ __half g_Wth[EOUT * CT];            // 8 MB  W^T hi
__device__ __half g_Wtl[EOUT * CT];            // 8 MB  W^T lo
__device__ float  g_Whp[KSPLIT * NV * EOUT];   // 14.7 MB split-K partials
__device__ float  g_Wh[NV * EOUT];             // 1.84 MB

__device__ __forceinline__ uint32_t smem_u32(const void* p) {
    uint32_t a;
    asm("{ .reg .u64 t; cvta.to.shared.u64 t, %1; cvt.u32.u64 %0, t; }" : "=r"(a) : "l"(p));
    return a;
}
#define CP_ASYNC16(dst, src) \
    asm volatile("cp.async.cg.shared.global [%0], [%1], 16;" :: "r"(dst), "l"(src))
#define CP_COMMIT() asm volatile("cp.async.commit_group;")
#define CP_WAIT0()  asm volatile("cp.async.wait_group 0;")

// ---------------------------------------------------------------------------
// W transpose + fp16 hi/lo split
// ---------------------------------------------------------------------------
__global__ __launch_bounds__(256) void transpose_W(const float* __restrict__ W) {
    __shared__ float tile[32][33];
    const int k0 = blockIdx.x * 32, o0 = blockIdx.y * 32;
    const int tx = threadIdx.x & 31, ty = threadIdx.x >> 5;
#pragma unroll
    for (int r = 0; r < 32; r += 8)
        tile[ty + r][tx] = W[(size_t)(k0 + ty + r) * EOUT + o0 + tx];
    __syncthreads();
#pragma unroll
    for (int r = 0; r < 32; r += 8) {
        const float x = tile[tx][ty + r];
        const __half hx = __float2half_rn(x);
        const __half lx = __float2half_rn(x - __half2float(hx));
        const size_t idx = (size_t)(o0 + ty + r) * CT + k0 + tx;
        g_Wth[idx] = hx;
        g_Wtl[idx] = lx;
    }
}

// ---------------------------------------------------------------------------
// fp16x3 GEMM via wmma, split-K. Grid (14, 1, 8), 512 threads (16 warps).
// Warp tile 64x32: mw = (wid>>3)*64, nw = (wid&7)*32.
// ---------------------------------------------------------------------------
__global__ __launch_bounds__(512, 1) void gemm_mma(const float* __restrict__ h) {
    extern __shared__ __half smh[];
    __half* const AHb = smh;                       // 2 stages ABUFH
    __half* const ALb = smh + 2 * ABUFH;
    __half* const BHb = smh + 4 * ABUFH;           // 2 stages BBUFH
    __half* const BLb = smh + 4 * ABUFH + 2 * BBUFH;

    const int tid = threadIdx.x, wid = tid >> 5, lane = tid & 31;
    const int m0 = blockIdx.x * BM, ks = blockIdx.z;
    const int kbase = ks * KSLICE;

    // ---- A gather: step r -> smem row (16r + wid), lane = k within BK ----
    int aBase[8];
#pragma unroll
    for (int r = 0; r < 8; r++) {
        const int row = 16 * r + wid;
        const int m = m0 + row;
        const int n = m / 7, v = m - n * 7;
        aBase[r] = n * CTV + v + lane * 7;
    }
    // ---- B cp.async geometry: j = r*512+tid over 1024; o=j>>2, kq=j&3 ----
    const uint32_t sm_base = smem_u32(smh);
    int bsrc[2];       // half index into g_Wt* (k base added at use)
    uint32_t bdstoff[2];  // byte offset within a B buffer
#pragma unroll
    for (int r = 0; r < 2; r++) {
        const int j = r * 512 + tid;
        const int o = j >> 2, kq = j & 3;
        bsrc[r] = o * CT + kq * 8;
        bdstoff[r] = (uint32_t)(o * SA + kq * 8) * 2;
    }

    wmma::fragment<wmma::accumulator, 16, 16, 16, float> acc[4][2];
#pragma unroll
    for (int mf = 0; mf < 4; mf++)
#pragma unroll
        for (int nf = 0; nf < 2; nf++) wmma::fill_fragment(acc[mf][nf], 0.f);

    const int mw = (wid >> 3) * 64;   // 0 or 64
    const int nw = (wid & 7) * 32;    // 0..224

    // ---- prologue: stage 0 ----
    float aR[8];
    {
        const int k7 = kbase * 7;
#pragma unroll
        for (int r = 0; r < 8; r++) aR[r] = h[(size_t)(aBase[r] + k7)];
        const uint32_t bh0 = sm_base + (4 * ABUFH) * 2;
        const uint32_t bl0 = sm_base + (4 * ABUFH + 2 * BBUFH) * 2;
#pragma unroll
        for (int r = 0; r < 2; r++) {
            CP_ASYNC16(bh0 + bdstoff[r], (const char*)&g_Wth[(size_t)bsrc[r] + kbase]);
            CP_ASYNC16(bl0 + bdstoff[r], (const char*)&g_Wtl[(size_t)bsrc[r] + kbase]);
        }
        CP_COMMIT();
        // STS A stage 0
        __half* const ah = AHb;
        __half* const al = ALb;
#pragma unroll
        for (int r = 0; r < 8; r++) {
            const int d = (16 * r + wid) * SA + lane;
            const float x = aR[r];
            const __half hx = __float2half_rn(x);
            ah[d] = hx;
            al[d] = __float2half_rn(x - __half2float(hx));
        }
        CP_WAIT0();
        __syncthreads();
    }

#pragma unroll 1
    for (int s = 0; s < NST; s++) {
        const int buf = s & 1;
        const int nxt = buf ^ 1;
        __half* const ah = AHb + buf * ABUFH;
        __half* const al = ALb + buf * ABUFH;
        __half* const bh = BHb + buf * BBUFH;
        __half* const bl = BLb + buf * BBUFH;

        // issue loads for stage s+1 (A into regs, B via cp.async)
        const bool more = (s + 1 < NST);
        if (more) {
            const int kn = kbase + (s + 1) * BK;
            const int k7 = kn * 7;
#pragma unroll
            for (int r = 0; r < 8; r++) aR[r] = h[(size_t)(aBase[r] + k7)];
            const uint32_t bhn = sm_base + (4 * ABUFH + nxt * BBUFH) * 2;
            const uint32_t bln = sm_base + (4 * ABUFH + (2 + nxt) * BBUFH) * 2;
#pragma unroll
            for (int r = 0; r < 2; r++) {
                CP_ASYNC16(bhn + bdstoff[r], (const char*)&g_Wth[(size_t)bsrc[r] + kn]);
                CP_ASYNC16(bln + bdstoff[r], (const char*)&g_Wtl[(size_t)bsrc[r] + kn]);
            }
        }
        CP_COMMIT();

        // compute stage s
#pragma unroll
        for (int c = 0; c < 2; c++) {
            const int kk = c * 16;
            wmma::fragment<wmma::matrix_a, 16, 16, 16, __half, wmma::row_major> aH[4], aL[4];
#pragma unroll
            for (int mf = 0; mf < 4; mf++) {
                wmma::load_matrix_sync(aH[mf], ah + (mw + mf * 16) * SA + kk, SA);
                wmma::load_matrix_sync(aL[mf], al + (mw + mf * 16) * SA + kk, SA);
            }
            wmma::fragment<wmma::matrix_b, 16, 16, 16, __half, wmma::col_major> bH[2], bL[2];
#pragma unroll
            for (int nf = 0; nf < 2; nf++) {
                wmma::load_matrix_sync(bH[nf], bh + (nw + nf * 16) * SA + kk, SA);
                wmma::load_matrix_sync(bL[nf], bl + (nw + nf * 16) * SA + kk, SA);
            }
#pragma unroll
            for (int mf = 0; mf < 4; mf++)
#pragma unroll
                for (int nf = 0; nf < 2; nf++) {
                    wmma::mma_sync(acc[mf][nf], aH[mf], bH[nf], acc[mf][nf]);
                    wmma::mma_sync(acc[mf][nf], aH[mf], bL[nf], acc[mf][nf]);
                    wmma::mma_sync(acc[mf][nf], aL[mf], bH[nf], acc[mf][nf]);
                }
        }

        // STS A for stage s+1 into the other buffer
        if (more) {
            __half* const ahn = AHb + nxt * ABUFH;
            __half* const aln = ALb + nxt * ABUFH;
#pragma unroll
            for (int r = 0; r < 8; r++) {
                const int d = (16 * r + wid) * SA + lane;
                const float x = aR[r];
                const __half hx = __float2half_rn(x);
                ahn[d] = hx;
                aln[d] = __float2half_rn(x - __half2float(hx));
            }
        }
        CP_WAIT0();
        __syncthreads();
    }

    // epilogue: store partials
#pragma unroll
    for (int mf = 0; mf < 4; mf++)
#pragma unroll
        for (int nf = 0; nf < 2; nf++) {
            float* dst = g_Whp + ((size_t)ks * NV + m0 + mw + mf * 16) * EOUT
                       + nw + nf * 16;
            wmma::store_matrix_sync(dst, acc[mf][nf], EOUT, wmma::mem_row_major);
        }
}

// ---------------------------------------------------------------------------
// Split-K reduction
// ---------------------------------------------------------------------------
__global__ __launch_bounds__(256) void reduce_k() {
    const int i = blockIdx.x * 256 + threadIdx.x;
    const float4* p = reinterpret_cast<const float4*>(g_Whp);
    float4 s = p[i];
#pragma unroll
    for (int k = 1; k < KSPLIT; k++) {
        const float4 t = p[(size_t)k * (NV * EOUT / 4) + i];
        s.x += t.x; s.y += t.y; s.z += t.z; s.w += t.w;
    }
    reinterpret_cast<float4*>(g_Wh)[i] = s;
}

// ---------------------------------------------------------------------------
// Per-batch attention epilogue (adjacency normalization fused in)
// ---------------------------------------------------------------------------
__global__ __launch_bounds__(256) void attn_kernel(const float* __restrict__ a,
                                                   const float* __restrict__ Bp,
                                                   float* __restrict__ out) {
    const int n = blockIdx.x;
    const int t = threadIdx.x;
    const float* Wh = g_Wh + n * (VN * EOUT);

    __shared__ float adj[49];
    __shared__ float amin, amax;
    __shared__ float dis[7];
    __shared__ float s1[8], s2[8];
    __shared__ float smx[7][7];
    __shared__ float att[7][7];

    // --- adjacency normalization (cheap, per block) ---
    if (t < 49) {
        const int i = t / 7, j = t - (t / 7) * 7;
        adj[t] = Bp[t] + 1e-6f + (i == j ? 1.f : 0.f);
    }
    __syncthreads();
    if (t == 0) {
        float mn = adj[0], mx = adj[0];
        for (int s = 1; s < 49; s++) { mn = fminf(mn, adj[s]); mx = fmaxf(mx, adj[s]); }
        amin = mn; amax = mx;
    }
    __syncthreads();
    if (t < 49) adj[t] = (adj[t] - amin) / (amax - amin);
    __syncthreads();
    if (t < 7) {
        float s = 0.f;
        for (int j = 0; j < 7; j++) s += adj[t * 7 + j];
        dis[t] = 1.0f / sqrtf(s);
    }
    __syncthreads();
    if (t < 49) {
        const int i = t / 7, j = t - (t / 7) * 7;
        adj[t] = dis[i] * adj[t] * dis[j];
    }

    // --- s1/s2 dot products ---
    const int w = t >> 5, l = t & 31;
    if (w < 7) {
        float p1 = 0.f, p2 = 0.f;
#pragma unroll
        for (int o = l; o < EOUT; o += 32) {
            const float x = Wh[w * EOUT + o];
            p1 += x * a[o];
            p2 += x * a[EOUT + o];
        }
#pragma unroll
        for (int off = 16; off > 0; off >>= 1) {
            p1 += __shfl_down_sync(0xffffffffu, p1, off);
            p2 += __shfl_down_sync(0xffffffffu, p2, off);
        }
        if (l == 0) { s1[w] = p1; s2[w] = p2; }
    }
    __syncthreads();

    if (t < 7) {
        float e[7];
        float mx = -1e30f;
#pragma unroll
        for (int u = 0; u < 7; u++) {
            float x = s1[t] + s2[u];
            x = (x > 0.f) ? x : ALPHA * x;
            e[u] = x;
            mx = fmaxf(mx, x);
        }
        float s = 0.f;
#pragma unroll
        for (int u = 0; u < 7; u++) { e[u] = expf(e[u] - mx); s += e[u]; }
        const float inv = 1.f / s;
#pragma unroll
        for (int u = 0; u < 7; u++) smx[t][u] = e[u] * inv;
    }
    __syncthreads();

    if (t < 49) {
        const int i = t / 7, j = t - (t / 7) * 7;
        float s = 0.f;
#pragma unroll
        for (int u = 0; u < 7; u++) s += adj[i * 7 + u] * smx[u][j];
        att[i][j] = s;
    }
    __syncthreads();

    float whu[7];
#pragma unroll
    for (int u = 0; u < 7; u++) whu[u] = Wh[u * EOUT + t];

#pragma unroll
    for (int v = 0; v < 7; v++) {
        float hp = 0.f;
#pragma unroll
        for (int u = 0; u < 7; u++) hp = fmaf(att[v][u], whu[u], hp);
        const float r = (hp > 0.f) ? hp : expm1f(hp);
        out[n * (VN * EOUT) + v * EOUT + t] = r;
    }
}

// ---------------------------------------------------------------------------
extern "C" void kernel_launch(void* const* d_in, const int* in_sizes, int n_in,
                              void* d_out, int out_size) {
    const float* h  = (const float*)d_in[0];
    const float* W  = (const float*)d_in[1];
    const float* a  = (const float*)d_in[2];
    const float* Bp = (const float*)d_in[3];
    float* out = (float*)d_out;

    const int smem_bytes = (4 * ABUFH + 4 * BBUFH) * 2;   // 122880
    cudaFuncSetAttribute(gemm_mma, cudaFuncAttributeMaxDynamicSharedMemorySize, smem_bytes);

    transpose_W<<<dim3(CT / 32, EOUT / 32), 256>>>(W);
    gemm_mma<<<dim3(NV / BM, 1, KSPLIT), 512, smem_bytes>>>(h);
    reduce_k<<<NV * EOUT / 4 / 256, 256>>>();
    attn_kernel<<<NB, 256>>>(a, Bp, out);
}